// round 7
// baseline (speedup 1.0000x reference)
#include <cuda_runtime.h>

// LIF, tau=2, hard reset to 0, decay_input=False:
//   v = (v + x_t) - v*0.5 ; s = (v>=1) ; out=s ; v = s?0:v
// Pure streaming: 268MB read + 268MB write, T=4 carried in registers.
// R4/R6: persistent grid-stride kernel, exactly one wave (148 SMs x 8 CTAs),
// killing ~13 wave transitions + per-wave tail spread. Keeps front-batched
// 4x LDG.128 + streaming cache hints per iteration. (R6 = R4 resubmit after
// infra failure; the change has not yet been measured.)

__device__ __forceinline__ float4 lif_step(float4 xt, float4& v) {
    // exact reference order: v = (v + x) - v*0.5, FMA contraction blocked
    float nx = __fadd_rn(__fadd_rn(v.x, xt.x), -__fmul_rn(v.x, 0.5f));
    float ny = __fadd_rn(__fadd_rn(v.y, xt.y), -__fmul_rn(v.y, 0.5f));
    float nz = __fadd_rn(__fadd_rn(v.z, xt.z), -__fmul_rn(v.z, 0.5f));
    float nw = __fadd_rn(__fadd_rn(v.w, xt.w), -__fmul_rn(v.w, 0.5f));
    float4 s;
    s.x = (nx >= 1.0f) ? 1.0f : 0.0f;
    s.y = (ny >= 1.0f) ? 1.0f : 0.0f;
    s.z = (nz >= 1.0f) ? 1.0f : 0.0f;
    s.w = (nw >= 1.0f) ? 1.0f : 0.0f;
    v.x = (s.x != 0.0f) ? 0.0f : nx;
    v.y = (s.y != 0.0f) ? 0.0f : ny;
    v.z = (s.z != 0.0f) ? 0.0f : nz;
    v.w = (s.w != 0.0f) ? 0.0f : nw;
    return s;
}

__global__ void __launch_bounds__(256)
lif_kernel(const float4* __restrict__ x, float4* __restrict__ out, int n4) {
    const size_t n = (size_t)n4;
    const int stride = gridDim.x * blockDim.x;

    for (int i = blockIdx.x * blockDim.x + threadIdx.x; i < n4; i += stride) {
        // Front-batch all 4 independent loads: 4 LDG.128 in flight.
        float4 x0 = __ldcs(&x[i]);
        float4 x1 = __ldcs(&x[n + i]);
        float4 x2 = __ldcs(&x[2 * n + i]);
        float4 x3 = __ldcs(&x[3 * n + i]);

        float4 v = make_float4(0.f, 0.f, 0.f, 0.f);

        float4 s0 = lif_step(x0, v);
        __stcs(&out[i], s0);
        float4 s1 = lif_step(x1, v);
        __stcs(&out[n + i], s1);
        float4 s2 = lif_step(x2, v);
        __stcs(&out[2 * n + i], s2);
        float4 s3 = lif_step(x3, v);
        __stcs(&out[3 * n + i], s3);
    }
}

extern "C" void kernel_launch(void* const* d_in, const int* in_sizes, int n_in,
                              void* d_out, int out_size) {
    const float* x = (const float*)d_in[0];
    float* out = (float*)d_out;

    const int T = 4;
    int n_total = in_sizes[0];          // 67,108,864
    int n_per_step = n_total / T;       // 16,777,216
    int n4 = n_per_step / 4;            // 4,194,304 float4 lanes

    // One full wave: 148 SMs x 8 CTAs. Grid-stride covers ~14 iters/thread.
    int threads = 256;
    int blocks = 148 * 8;               // 1184
    lif_kernel<<<blocks, threads>>>((const float4*)x, (float4*)out, n4);
}

// round 9
// speedup vs baseline: 1.2430x; 1.2430x over previous
#include <cuda_runtime.h>

// LIF, tau=2, hard reset to 0, decay_input=False:
//   v = (v + x_t) - v*0.5 ; s = (v>=1) ; out=s ; v = s?0:v
// Pure streaming: 268MB read + 268MB write, T=4 carried in registers.
// R7: REVERT to flat multi-wave launch (R3 structure, measured best 74.5us
// kernel / 82.7% DRAM). Persistent one-wave variant regressed (89us): flat
// launches get cross-CTA load/compute overlap from the CTA scheduler for
// free; grid-stride serialized loads behind compute per warp.
// Single probe this round: block=512 (same 64 resident warps/SM, half the
// CTA dispatch events).

__device__ __forceinline__ float4 lif_step(float4 xt, float4& v) {
    // exact reference order: v = (v + x) - v*0.5, FMA contraction blocked
    float nx = __fadd_rn(__fadd_rn(v.x, xt.x), -__fmul_rn(v.x, 0.5f));
    float ny = __fadd_rn(__fadd_rn(v.y, xt.y), -__fmul_rn(v.y, 0.5f));
    float nz = __fadd_rn(__fadd_rn(v.z, xt.z), -__fmul_rn(v.z, 0.5f));
    float nw = __fadd_rn(__fadd_rn(v.w, xt.w), -__fmul_rn(v.w, 0.5f));
    float4 s;
    s.x = (nx >= 1.0f) ? 1.0f : 0.0f;
    s.y = (ny >= 1.0f) ? 1.0f : 0.0f;
    s.z = (nz >= 1.0f) ? 1.0f : 0.0f;
    s.w = (nw >= 1.0f) ? 1.0f : 0.0f;
    v.x = (s.x != 0.0f) ? 0.0f : nx;
    v.y = (s.y != 0.0f) ? 0.0f : ny;
    v.z = (s.z != 0.0f) ? 0.0f : nz;
    v.w = (s.w != 0.0f) ? 0.0f : nw;
    return s;
}

__global__ void __launch_bounds__(512)
lif_kernel(const float4* __restrict__ x, float4* __restrict__ out, int n4) {
    int i = blockIdx.x * blockDim.x + threadIdx.x;
    if (i >= n4) return;

    const size_t n = (size_t)n4;

    // Front-batch all 4 independent loads: 4 LDG.128 in flight per thread.
    float4 x0 = __ldcs(&x[i]);
    float4 x1 = __ldcs(&x[n + i]);
    float4 x2 = __ldcs(&x[2 * n + i]);
    float4 x3 = __ldcs(&x[3 * n + i]);

    float4 v = make_float4(0.f, 0.f, 0.f, 0.f);

    float4 s0 = lif_step(x0, v);
    __stcs(&out[i], s0);
    float4 s1 = lif_step(x1, v);
    __stcs(&out[n + i], s1);
    float4 s2 = lif_step(x2, v);
    __stcs(&out[2 * n + i], s2);
    float4 s3 = lif_step(x3, v);
    __stcs(&out[3 * n + i], s3);
}

extern "C" void kernel_launch(void* const* d_in, const int* in_sizes, int n_in,
                              void* d_out, int out_size) {
    const float* x = (const float*)d_in[0];
    float* out = (float*)d_out;

    const int T = 4;
    int n_total = in_sizes[0];          // 67,108,864
    int n_per_step = n_total / T;       // 16,777,216
    int n4 = n_per_step / 4;            // 4,194,304 float4 lanes

    int threads = 512;
    int blocks = (n4 + threads - 1) / threads;   // 8192
    lif_kernel<<<blocks, threads>>>((const float4*)x, (float4*)out, n4);
}

// round 11
// speedup vs baseline: 1.2493x; 1.0051x over previous
#include <cuda_runtime.h>

// LIF, tau=2, hard reset to 0, decay_input=False:
//   v = (v + x_t) - v*0.5 ; s = (v>=1) ; out=s ; v = s?0:v
// Pure streaming: 268MB read + 268MB write, T=4 carried in registers.
// R9: flat launch, block=256 (measured-best shape; 512 and persistent both
// regressed), streaming hints, and 2 float4 per thread with ALL 8 loads
// front-batched (MLP_p1=8, no loop -> no serialization like R6).
// Second float4 at +blockDim keeps every LDG/STG.128 coalesced.

__device__ __forceinline__ float4 lif_step(float4 xt, float4& v) {
    // exact reference order: v = (v + x) - v*0.5, FMA contraction blocked
    float nx = __fadd_rn(__fadd_rn(v.x, xt.x), -__fmul_rn(v.x, 0.5f));
    float ny = __fadd_rn(__fadd_rn(v.y, xt.y), -__fmul_rn(v.y, 0.5f));
    float nz = __fadd_rn(__fadd_rn(v.z, xt.z), -__fmul_rn(v.z, 0.5f));
    float nw = __fadd_rn(__fadd_rn(v.w, xt.w), -__fmul_rn(v.w, 0.5f));
    float4 s;
    s.x = (nx >= 1.0f) ? 1.0f : 0.0f;
    s.y = (ny >= 1.0f) ? 1.0f : 0.0f;
    s.z = (nz >= 1.0f) ? 1.0f : 0.0f;
    s.w = (nw >= 1.0f) ? 1.0f : 0.0f;
    v.x = (s.x != 0.0f) ? 0.0f : nx;
    v.y = (s.y != 0.0f) ? 0.0f : ny;
    v.z = (s.z != 0.0f) ? 0.0f : nz;
    v.w = (s.w != 0.0f) ? 0.0f : nw;
    return s;
}

__global__ void __launch_bounds__(256)
lif_kernel(const float4* __restrict__ x, float4* __restrict__ out, int n4) {
    // Each CTA covers 2*blockDim float4 lanes: [base, base+2*256).
    int base = blockIdx.x * (blockDim.x * 2) + threadIdx.x;
    int ia = base;                      // lane A
    int ib = base + blockDim.x;         // lane B (coalesced with neighbors)
    if (ib >= n4 && ia >= n4) return;

    const size_t n = (size_t)n4;
    bool vb = (ib < n4);

    // Front-batch 8 independent LDG.128 (4 timesteps x 2 lanes).
    float4 a0 = __ldcs(&x[ia]);
    float4 a1 = __ldcs(&x[n + ia]);
    float4 a2 = __ldcs(&x[2 * n + ia]);
    float4 a3 = __ldcs(&x[3 * n + ia]);
    float4 b0, b1, b2, b3;
    if (vb) {
        b0 = __ldcs(&x[ib]);
        b1 = __ldcs(&x[n + ib]);
        b2 = __ldcs(&x[2 * n + ib]);
        b3 = __ldcs(&x[3 * n + ib]);
    }

    float4 va = make_float4(0.f, 0.f, 0.f, 0.f);
    float4 vB = make_float4(0.f, 0.f, 0.f, 0.f);

    float4 sa0 = lif_step(a0, va);
    __stcs(&out[ia], sa0);
    float4 sa1 = lif_step(a1, va);
    __stcs(&out[n + ia], sa1);
    float4 sa2 = lif_step(a2, va);
    __stcs(&out[2 * n + ia], sa2);
    float4 sa3 = lif_step(a3, va);
    __stcs(&out[3 * n + ia], sa3);

    if (vb) {
        float4 sb0 = lif_step(b0, vB);
        __stcs(&out[ib], sb0);
        float4 sb1 = lif_step(b1, vB);
        __stcs(&out[n + ib], sb1);
        float4 sb2 = lif_step(b2, vB);
        __stcs(&out[2 * n + ib], sb2);
        float4 sb3 = lif_step(b3, vB);
        __stcs(&out[3 * n + ib], sb3);
    }
}

extern "C" void kernel_launch(void* const* d_in, const int* in_sizes, int n_in,
                              void* d_out, int out_size) {
    const float* x = (const float*)d_in[0];
    float* out = (float*)d_out;

    const int T = 4;
    int n_total = in_sizes[0];          // 67,108,864
    int n_per_step = n_total / T;       // 16,777,216
    int n4 = n_per_step / 4;            // 4,194,304 float4 lanes

    int threads = 256;
    int per_cta = threads * 2;          // 512 float4 per CTA
    int blocks = (n4 + per_cta - 1) / per_cta;   // 8192
    lif_kernel<<<blocks, threads>>>((const float4*)x, (float4*)out, n4);
}